// round 10
// baseline (speedup 1.0000x reference)
#include <cuda_runtime.h>
#include <math.h>

#define BB 8
#define CC 64
#define NN 4096
#define TOT (BB*CC*NN)
#define TILE_N 128
#define NTB (NN/TILE_N)      // 32 n-tiles per batch
#define TILES (BB*NTB)       // 256 blocks

typedef unsigned long long u64;

// Scratch (allocation-free: __device__ globals)
__device__ float g_z[TOT];                 // z = W @ x (8 MB)
__device__ float g_psum[BB*CC*NTB];        // partial Σz   [b][o][nb]
__device__ float g_psq [BB*CC*NTB];        // partial Σz²  [b][o][nb]
__device__ float g_spart[TILES];           // partial s_b  [b][nb]
__device__ float g_scale[BB*CC];
__device__ float g_bias [BB*CC];

// ---- f32x2 packed helpers (sm_103a) ----
__device__ __forceinline__ u64 ffma2(u64 a, u64 b, u64 c) {
    u64 d;
    asm("fma.rn.f32x2 %0, %1, %2, %3;" : "=l"(d) : "l"(a), "l"(b), "l"(c));
    return d;
}
__device__ __forceinline__ u64 packdup(float v) {
    u64 r;
    asm("mov.b64 %0, {%1, %2};" : "=l"(r) : "f"(v), "f"(v));
    return r;
}
__device__ __forceinline__ void unpack2(u64 v, float& lo, float& hi) {
    asm("mov.b64 {%0, %1}, %2;" : "=f"(lo), "=f"(hi) : "l"(v));
}

// ============================================================================
// K1: z[b,o,n] = Σ_c W[o,c]·x[b,c,n].  Tile 64o × 128n, 512 threads,
// 2 CTAs/SM (64KB smem, regs capped by launch bounds) -> 32 warps/SM.
// Warp wid owns o-group [4*wid, 4*wid+4) -> W operands BROADCAST LDS;
// lane owns 4 consecutive n (1 LDS.128 per c). 8 FFMA2 per lane per c.
// ============================================================================
__global__ __launch_bounds__(512, 2)
void k1_gemm(const float* __restrict__ x,
             const float* __restrict__ wvec,
             const float* __restrict__ W)
{
    extern __shared__ char sm[];
    u64*   wt2 = (u64*)sm;                  // [64][64] dup pairs (32 KB)
    float* xs  = (float*)(sm + 32768);      // [64][128]           (32 KB)
    __shared__ float sred[4];

    const int t    = threadIdx.x;
    const int tile = blockIdx.x;
    const int b    = tile >> 5;
    const int nb   = tile & 31;
    const int n0   = nb * TILE_N;

    // tanh(w)² partial for this 128-wide n-slice (warps 0-3)
    if (t < 128) {
        float vv = tanhf(wvec[b * NN + n0 + t]);
        vv = fmaxf(vv, 0.f);
        float sp = vv * vv;
        #pragma unroll
        for (int off = 16; off > 0; off >>= 1)
            sp += __shfl_xor_sync(0xFFFFFFFFu, sp, off);
        if ((t & 31) == 0) sred[t >> 5] = sp;
    }

    // Load W dup-packed (transposed): wt2[c][o] = {W[o,c], W[o,c]}
    #pragma unroll
    for (int i = 0; i < 8; i++) {
        int idx = i * 512 + t;
        wt2[(idx & 63) * 64 + (idx >> 6)] = packdup(W[idx]);
    }
    // Load x tile: 64 c-rows × 32 float4
    const float4* x4 = (const float4*)(x + ((size_t)b * CC) * NN + n0);
    #pragma unroll
    for (int i = 0; i < 4; i++) {
        int idx = i * 512 + t;
        int c = idx >> 5, j = idx & 31;
        ((float4*)(xs + c * TILE_N))[j] = x4[c * (NN / 4) + j];
    }
    __syncthreads();
    if (t == 0) g_spart[tile] = (sred[0] + sred[1]) + (sred[2] + sred[3]);

    const int wid = t >> 5, lane = t & 31;   // wid 0-15 = o-group (4 o's)
    const int o0 = wid * 4;
    const float* xbase = xs + lane * 4;

    u64 acc[4][2];
    #pragma unroll
    for (int i = 0; i < 4; i++) { acc[i][0] = 0ull; acc[i][1] = 0ull; }

    #pragma unroll 8
    for (int c = 0; c < 64; c++) {
        const u64* wrow = wt2 + c * 64 + o0;
        ulonglong2 w01 = *(const ulonglong2*)(wrow);      // broadcast
        ulonglong2 w23 = *(const ulonglong2*)(wrow + 2);  // broadcast
        ulonglong2 xv  = *(const ulonglong2*)(xbase + c * TILE_N);
        acc[0][0] = ffma2(w01.x, xv.x, acc[0][0]);
        acc[0][1] = ffma2(w01.x, xv.y, acc[0][1]);
        acc[1][0] = ffma2(w01.y, xv.x, acc[1][0]);
        acc[1][1] = ffma2(w01.y, xv.y, acc[1][1]);
        acc[2][0] = ffma2(w23.x, xv.x, acc[2][0]);
        acc[2][1] = ffma2(w23.x, xv.y, acc[2][1]);
        acc[3][0] = ffma2(w23.y, xv.x, acc[3][0]);
        acc[3][1] = ffma2(w23.y, xv.y, acc[3][1]);
    }

    // Write z + per-o stats (full-warp reduce over the 128 n's)
    #pragma unroll
    for (int i = 0; i < 4; i++) {
        const int o = o0 + i;
        float* zo = g_z + ((size_t)(b * CC + o)) * NN + n0 + lane * 4;
        ulonglong2 p; p.x = acc[i][0]; p.y = acc[i][1];
        *(ulonglong2*)zo = p;

        float v0, v1, v2, v3;
        unpack2(acc[i][0], v0, v1);
        unpack2(acc[i][1], v2, v3);
        float s = (v0 + v1) + (v2 + v3);
        float q = fmaf(v0, v0, fmaf(v1, v1, fmaf(v2, v2, v3 * v3)));
        #pragma unroll
        for (int off = 16; off > 0; off >>= 1) {
            s += __shfl_xor_sync(0xFFFFFFFFu, s, off);
            q += __shfl_xor_sync(0xFFFFFFFFu, q, off);
        }
        if (lane == 0) {
            g_psum[(b * CC + o) * NTB + nb] = s;
            g_psq [(b * CC + o) * NTB + nb] = q;
        }
    }
}

// ============================================================================
// K2: reduce partials -> per-(b,o) scale/bias. One block, 512 threads.
// ============================================================================
__global__ __launch_bounds__(512)
void k2_finalize(const float* __restrict__ conv_b,
                 const float* __restrict__ gamma,
                 const float* __restrict__ beta)
{
    __shared__ float s_sh[BB];
    __shared__ float zZ[BB*CC], zQ[BB*CC];
    const int t = threadIdx.x;

    // s_b: warp w reduces batch w's 32 contiguous tile partials (t<256)
    if (t < 256) {
        const int w = t >> 5, l = t & 31;
        float sp = g_spart[w * NTB + l];
        #pragma unroll
        for (int off = 16; off > 0; off >>= 1)
            sp += __shfl_xor_sync(0xFFFFFFFFu, sp, off);
        if (l == 0) s_sh[w] = sp;
    }

    // Z,Q: thread t reduces (b,o)=t's 32 contiguous partials (float4 x8 each)
    {
        const float4* p4 = (const float4*)(g_psum + t * NTB);
        const float4* q4 = (const float4*)(g_psq  + t * NTB);
        float Z = 0.f, Q = 0.f;
        #pragma unroll
        for (int i = 0; i < NTB / 4; i++) {
            float4 a = p4[i], c = q4[i];
            Z += (a.x + a.y) + (a.z + a.w);
            Q += (c.x + c.y) + (c.z + c.w);
        }
        zZ[t] = Z; zQ[t] = Q;
    }
    __syncthreads();

    if (t < CC) {
        const int o = t;
        float cb = conv_b[o];
        float alpha[BB], offv[BB];
        float mean_acc = 0.f, sq_acc = 0.f;
        #pragma unroll
        for (int bb = 0; bb < BB; bb++) {
            float s = s_sh[bb];
            float a = 1.f / (1.f + (float)NN * s);
            float Z = zZ[bb * CC + o];
            float Q = zQ[bb * CC + o];
            float off = a * s * Z + cb;
            alpha[bb] = a; offv[bb] = off;
            mean_acc += a * Z + (float)NN * off;
            sq_acc   += a * a * Q + 2.f * a * off * Z + (float)NN * off * off;
        }
        const float inv_cnt = 1.f / (float)(BB * NN);
        float mean = mean_acc * inv_cnt;
        float var  = sq_acc * inv_cnt - mean * mean;
        float invstd = rsqrtf(var + 1e-5f);
        float g  = gamma[o] * invstd;
        float be = beta[o];
        #pragma unroll
        for (int bb = 0; bb < BB; bb++) {
            g_scale[bb * CC + o] = alpha[bb] * g;
            g_bias [bb * CC + o] = (offv[bb] - mean) * g + be;
        }
    }
}

// ============================================================================
// K3: pure stream, single wave. 128 blocks × 512 threads; block handles 4
// rows; each thread 8 independent float4 (MLP=8).
// ============================================================================
__global__ __launch_bounds__(512)
void k3_epilogue(float* __restrict__ out)
{
    const int t    = threadIdx.x;
    const int row  = blockIdx.x * 4 + (t >> 7);   // 4 rows per block
    const int col  = t & 127;                     // f4 lane within row
    const float sc = g_scale[row];
    const float bi = g_bias[row];
    const float4* z4 = (const float4*)(g_z + (size_t)row * NN);
    float4* o4 = (float4*)(out + (size_t)row * NN);

    float4 v[8];
    #pragma unroll
    for (int i = 0; i < 8; i++) v[i] = z4[col + i * 128];
    #pragma unroll
    for (int i = 0; i < 8; i++) {
        float4 r;
        r.x = fmaxf(fmaf(sc, v[i].x, bi), 0.f);
        r.y = fmaxf(fmaf(sc, v[i].y, bi), 0.f);
        r.z = fmaxf(fmaf(sc, v[i].z, bi), 0.f);
        r.w = fmaxf(fmaf(sc, v[i].w, bi), 0.f);
        o4[col + i * 128] = r;
    }
}

extern "C" void kernel_launch(void* const* d_in, const int* in_sizes, int n_in,
                              void* d_out, int out_size) {
    const float* x      = (const float*)d_in[0];  // [8,64,4096,1]
    const float* w      = (const float*)d_in[1];  // [8,4096]
    const float* conv_w = (const float*)d_in[2];  // [64,64,1,1]
    const float* conv_b = (const float*)d_in[3];  // [64]
    const float* gamma  = (const float*)d_in[4];  // [64]
    const float* beta   = (const float*)d_in[5];  // [64]
    float* out = (float*)d_out;

    cudaFuncSetAttribute(k1_gemm,
                         cudaFuncAttributeMaxDynamicSharedMemorySize, 65536);
    k1_gemm<<<TILES, 512, 65536>>>(x, w, conv_w);
    k2_finalize<<<1, 512>>>(conv_b, gamma, beta);
    k3_epilogue<<<BB * CC / 4, 512>>>(out);
}

// round 11
// speedup vs baseline: 1.2738x; 1.2738x over previous
#include <cuda_runtime.h>
#include <math.h>

#define BB 8
#define CC 64
#define NN 4096
#define TOT (BB*CC*NN)
#define TILE_N 256
#define NTB (NN/TILE_N)      // 16 n-tiles per batch
#define TILES (BB*NTB)       // 128 blocks

typedef unsigned long long u64;

// Scratch (allocation-free: __device__ globals)
__device__ float g_z[TOT];                 // z = W @ x (8 MB)
__device__ float g_psum[BB*CC*NTB];        // partial Σz   [b][o][nb]
__device__ float g_psq [BB*CC*NTB];        // partial Σz²  [b][o][nb]
__device__ float g_spart[TILES];           // partial s_b  [b][nb]
__device__ float g_scale[BB*CC];
__device__ float g_bias [BB*CC];

// ---- f32x2 packed helpers (sm_103a) ----
__device__ __forceinline__ u64 ffma2(u64 a, u64 b, u64 c) {
    u64 d;
    asm("fma.rn.f32x2 %0, %1, %2, %3;" : "=l"(d) : "l"(a), "l"(b), "l"(c));
    return d;
}
__device__ __forceinline__ u64 packdup(float v) {
    u64 r;
    asm("mov.b64 %0, {%1, %2};" : "=l"(r) : "f"(v), "f"(v));
    return r;
}
__device__ __forceinline__ void unpack2(u64 v, float& lo, float& hi) {
    asm("mov.b64 {%0, %1}, %2;" : "=f"(lo), "=f"(hi) : "l"(v));
}
__device__ __forceinline__ void cpa16(void* smem, const void* g) {
    unsigned int a = (unsigned int)__cvta_generic_to_shared(smem);
    asm volatile("cp.async.cg.shared.global [%0], [%1], 16;" :: "r"(a), "l"(g));
}

// ============================================================================
// K1: z[b,o,n] = Σ_c W[o,c]·x[b,c,n].  Tile 64o × 256n, 256 threads, 1 CTA/SM.
// Warp w owns o∈[8w,8w+8) -> W operands BROADCAST LDS (1 cyc each);
// lane owns n chunks {lane*4..+4} and {128+lane*4..+4} -> 2 CONFLICT-FREE
// LDS.128 per c (banks 4l..4l+3).  32 FFMA2 per lane per c  => FMA-bound.
// x tile arrives via cp.async overlapped with the W dup-pack.
// ============================================================================
__global__ __launch_bounds__(256, 1)
void k1_gemm(const float* __restrict__ x,
             const float* __restrict__ wvec,
             const float* __restrict__ W)
{
    extern __shared__ char sm[];
    u64*   wt2 = (u64*)sm;                  // [64][64] dup pairs (32 KB)
    float* xs  = (float*)(sm + 32768);      // [64][256]           (64 KB)
    __shared__ float sred[8];

    const int t    = threadIdx.x;
    const int tile = blockIdx.x;
    const int b    = tile >> 4;
    const int nb   = tile & 15;
    const int n0   = nb * TILE_N;

    // ---- kick off x tile loads (cp.async, L2->smem, no reg round-trip) ----
    const float4* x4 = (const float4*)(x + ((size_t)b * CC) * NN + n0);
    #pragma unroll
    for (int i = 0; i < 16; i++) {
        int idx = i * 256 + t;
        int c = idx >> 6, j = idx & 63;
        cpa16(xs + c * TILE_N + j * 4, x4 + c * (NN / 4) + j);
    }
    asm volatile("cp.async.commit_group;" ::: "memory");

    // ---- overlap: tanh(w)² partial for this 256-wide n-slice ----
    {
        float vv = tanhf(wvec[b * NN + n0 + t]);
        vv = fmaxf(vv, 0.f);
        float sp = vv * vv;
        #pragma unroll
        for (int off = 16; off > 0; off >>= 1)
            sp += __shfl_xor_sync(0xFFFFFFFFu, sp, off);
        if ((t & 31) == 0) sred[t >> 5] = sp;
    }

    // ---- overlap: W dup-packed (transposed): wt2[c][o] = {W[o,c], W[o,c]} --
    #pragma unroll
    for (int i = 0; i < 16; i++) {
        int idx = i * 256 + t;
        wt2[(idx & 63) * 64 + (idx >> 6)] = packdup(W[idx]);
    }

    asm volatile("cp.async.wait_group 0;" ::: "memory");
    __syncthreads();
    if (t == 0) {
        float s = 0.f;
        #pragma unroll
        for (int i = 0; i < 8; i++) s += sred[i];
        g_spart[tile] = s;
    }

    const int wid = t >> 5, lane = t & 31;
    const int o0 = wid * 8;
    const float* xA = xs + lane * 4;        // chunk A: n = lane*4..+4
    const float* xB = xs + 128 + lane * 4;  // chunk B: n = 128+lane*4..+4

    u64 acc[8][4];
    #pragma unroll
    for (int i = 0; i < 8; i++)
        #pragma unroll
        for (int j = 0; j < 4; j++) acc[i][j] = 0ull;

    #pragma unroll 4
    for (int c = 0; c < 64; c++) {
        const u64* wrow = wt2 + c * 64 + o0;
        ulonglong2 w01 = *(const ulonglong2*)(wrow);      // broadcast
        ulonglong2 w23 = *(const ulonglong2*)(wrow + 2);
        ulonglong2 w45 = *(const ulonglong2*)(wrow + 4);
        ulonglong2 w67 = *(const ulonglong2*)(wrow + 6);
        ulonglong2 xa = *(const ulonglong2*)(xA + c * TILE_N);  // conflict-free
        ulonglong2 xb = *(const ulonglong2*)(xB + c * TILE_N);  // conflict-free
        u64 wv[8] = {w01.x, w01.y, w23.x, w23.y, w45.x, w45.y, w67.x, w67.y};
        #pragma unroll
        for (int i = 0; i < 8; i++) {
            acc[i][0] = ffma2(wv[i], xa.x, acc[i][0]);
            acc[i][1] = ffma2(wv[i], xa.y, acc[i][1]);
            acc[i][2] = ffma2(wv[i], xb.x, acc[i][2]);
            acc[i][3] = ffma2(wv[i], xb.y, acc[i][3]);
        }
    }

    // Write z + per-o stats (full-warp reduce over the 256 n's)
    #pragma unroll
    for (int i = 0; i < 8; i++) {
        const int o = o0 + i;
        float* zo = g_z + ((size_t)(b * CC + o)) * NN + n0;
        ulonglong2 pa; pa.x = acc[i][0]; pa.y = acc[i][1];
        ulonglong2 pb; pb.x = acc[i][2]; pb.y = acc[i][3];
        *(ulonglong2*)(zo + lane * 4)       = pa;   // n chunk A
        *(ulonglong2*)(zo + 128 + lane * 4) = pb;   // n chunk B

        float v0, v1, v2, v3, v4, v5, v6, v7;
        unpack2(acc[i][0], v0, v1);
        unpack2(acc[i][1], v2, v3);
        unpack2(acc[i][2], v4, v5);
        unpack2(acc[i][3], v6, v7);
        float s = ((v0 + v1) + (v2 + v3)) + ((v4 + v5) + (v6 + v7));
        float q = fmaf(v0, v0, fmaf(v1, v1, fmaf(v2, v2, fmaf(v3, v3,
                  fmaf(v4, v4, fmaf(v5, v5, fmaf(v6, v6, v7 * v7)))))));
        #pragma unroll
        for (int off = 16; off > 0; off >>= 1) {
            s += __shfl_xor_sync(0xFFFFFFFFu, s, off);
            q += __shfl_xor_sync(0xFFFFFFFFu, q, off);
        }
        if (lane == 0) {
            g_psum[(b * CC + o) * NTB + nb] = s;
            g_psq [(b * CC + o) * NTB + nb] = q;
        }
    }
}

// ============================================================================
// K2: reduce partials -> per-(b,o) scale/bias. One block, 512 threads.
// ============================================================================
__global__ __launch_bounds__(512)
void k2_finalize(const float* __restrict__ conv_b,
                 const float* __restrict__ gamma,
                 const float* __restrict__ beta)
{
    __shared__ float s_sh[BB];
    __shared__ float zZ[BB*CC], zQ[BB*CC];
    const int t = threadIdx.x;

    // s_b: warp w reduces batch w's 16 tile partials (t<256, lanes 16-31 idle)
    if (t < 256) {
        const int w = t >> 5, l = t & 31;
        float sp = (l < NTB) ? g_spart[w * NTB + l] : 0.f;
        #pragma unroll
        for (int off = 16; off > 0; off >>= 1)
            sp += __shfl_xor_sync(0xFFFFFFFFu, sp, off);
        if (l == 0) s_sh[w] = sp;
    }

    // Z,Q: thread t reduces (b,o)=t's 16 contiguous partials (float4 x4 each)
    {
        const float4* p4 = (const float4*)(g_psum + t * NTB);
        const float4* q4 = (const float4*)(g_psq  + t * NTB);
        float Z = 0.f, Q = 0.f;
        #pragma unroll
        for (int i = 0; i < NTB / 4; i++) {
            float4 a = p4[i], c = q4[i];
            Z += (a.x + a.y) + (a.z + a.w);
            Q += (c.x + c.y) + (c.z + c.w);
        }
        zZ[t] = Z; zQ[t] = Q;
    }
    __syncthreads();

    if (t < CC) {
        const int o = t;
        float cb = conv_b[o];
        float alpha[BB], offv[BB];
        float mean_acc = 0.f, sq_acc = 0.f;
        #pragma unroll
        for (int bb = 0; bb < BB; bb++) {
            float s = s_sh[bb];
            float a = 1.f / (1.f + (float)NN * s);
            float Z = zZ[bb * CC + o];
            float Q = zQ[bb * CC + o];
            float off = a * s * Z + cb;
            alpha[bb] = a; offv[bb] = off;
            mean_acc += a * Z + (float)NN * off;
            sq_acc   += a * a * Q + 2.f * a * off * Z + (float)NN * off * off;
        }
        const float inv_cnt = 1.f / (float)(BB * NN);
        float mean = mean_acc * inv_cnt;
        float var  = sq_acc * inv_cnt - mean * mean;
        float invstd = rsqrtf(var + 1e-5f);
        float g  = gamma[o] * invstd;
        float be = beta[o];
        #pragma unroll
        for (int bb = 0; bb < BB; bb++) {
            g_scale[bb * CC + o] = alpha[bb] * g;
            g_bias [bb * CC + o] = (offv[bb] - mean) * g + be;
        }
    }
}

// ============================================================================
// K3: pure stream. 256 blocks × 256 threads; 2 rows/block; 8 indep f4/thread.
// ============================================================================
__global__ __launch_bounds__(256)
void k3_epilogue(float* __restrict__ out)
{
    const int t   = threadIdx.x;
    const int row = blockIdx.x * 2 + (t >> 7);   // 512 rows of 4096 floats
    const int col = t & 127;                     // f4 lane within row
    const float sc = g_scale[row];
    const float bi = g_bias[row];
    const float4* z4 = (const float4*)(g_z + (size_t)row * NN);
    float4* o4 = (float4*)(out + (size_t)row * NN);

    float4 v[8];
    #pragma unroll
    for (int i = 0; i < 8; i++) v[i] = z4[col + i * 128];
    #pragma unroll
    for (int i = 0; i < 8; i++) {
        float4 r;
        r.x = fmaxf(fmaf(sc, v[i].x, bi), 0.f);
        r.y = fmaxf(fmaf(sc, v[i].y, bi), 0.f);
        r.z = fmaxf(fmaf(sc, v[i].z, bi), 0.f);
        r.w = fmaxf(fmaf(sc, v[i].w, bi), 0.f);
        o4[col + i * 128] = r;
    }
}

extern "C" void kernel_launch(void* const* d_in, const int* in_sizes, int n_in,
                              void* d_out, int out_size) {
    const float* x      = (const float*)d_in[0];  // [8,64,4096,1]
    const float* w      = (const float*)d_in[1];  // [8,4096]
    const float* conv_w = (const float*)d_in[2];  // [64,64,1,1]
    const float* conv_b = (const float*)d_in[3];  // [64]
    const float* gamma  = (const float*)d_in[4];  // [64]
    const float* beta   = (const float*)d_in[5];  // [64]
    float* out = (float*)d_out;

    cudaFuncSetAttribute(k1_gemm,
                         cudaFuncAttributeMaxDynamicSharedMemorySize, 98304);
    k1_gemm<<<TILES, 256, 98304>>>(x, w, conv_w);
    k2_finalize<<<1, 512>>>(conv_b, gamma, beta);
    k3_epilogue<<<BB * CC / 2, 256>>>(out);
}

// round 12
// speedup vs baseline: 1.3304x; 1.0444x over previous
#include <cuda_runtime.h>
#include <math.h>

#define BB 8
#define CC 64
#define NN 4096
#define TILE_N 256
#define NTB (NN/TILE_N)      // 16 n-tiles per batch
#define TILES (BB*NTB)       // 128 blocks (=grid, 1 CTA/SM, co-resident)

typedef unsigned long long u64;

// Scratch (allocation-free: __device__ globals)
__device__ float g_psum[BB*CC*NTB];        // partial Σz   [b][o][nb]
__device__ float g_psq [BB*CC*NTB];        // partial Σz²  [b][o][nb]
__device__ float g_spart[TILES];           // partial s_b  [b][nb]
__device__ unsigned int g_bar = 0;         // monotonic grid barrier

// ---- f32x2 packed helpers (sm_103a) ----
__device__ __forceinline__ u64 ffma2(u64 a, u64 b, u64 c) {
    u64 d;
    asm("fma.rn.f32x2 %0, %1, %2, %3;" : "=l"(d) : "l"(a), "l"(b), "l"(c));
    return d;
}
__device__ __forceinline__ u64 packdup(float v) {
    u64 r;
    asm("mov.b64 %0, {%1, %2};" : "=l"(r) : "f"(v), "f"(v));
    return r;
}
__device__ __forceinline__ void unpack2(u64 v, float& lo, float& hi) {
    asm("mov.b64 {%0, %1}, %2;" : "=f"(lo), "=f"(hi) : "l"(v));
}
__device__ __forceinline__ void cpa16(void* smem, const void* g) {
    unsigned int a = (unsigned int)__cvta_generic_to_shared(smem);
    asm volatile("cp.async.cg.shared.global [%0], [%1], 16;" :: "r"(a), "l"(g));
}

// Replay-safe grid barrier (single round per launch). Callers must
// __threadfence() before if they published global writes.
__device__ __forceinline__ void grid_barrier() {
    __syncthreads();
    if (threadIdx.x == 0) {
        unsigned int old;
        asm volatile("atom.release.gpu.global.add.u32 %0, [%1], 1;"
                     : "=r"(old) : "l"(&g_bar) : "memory");
        unsigned int target = (old / TILES + 1u) * TILES;
        unsigned int v;
        do {
            asm volatile("ld.acquire.gpu.u32 %0, [%1];" : "=r"(v) : "l"(&g_bar));
        } while ((int)(v - target) < 0);
    }
    __syncthreads();
}

// ============================================================================
// Fused: GEMM (64o × 256n tile, warp-per-8o broadcast layout, FFMA2) ->
// stats partials -> grid barrier -> redundant per-block finalize ->
// epilogue from REGISTERS (no z round-trip, no extra launches).
// ============================================================================
__global__ __launch_bounds__(256, 1)
void fused(const float* __restrict__ x,
           const float* __restrict__ wvec,
           const float* __restrict__ W,
           const float* __restrict__ conv_b,
           const float* __restrict__ gamma,
           const float* __restrict__ beta,
           float* __restrict__ out)
{
    extern __shared__ char sm[];
    u64*   wt2 = (u64*)sm;                  // [64][64] dup pairs (32 KB)
    float* xs  = (float*)(sm + 32768);      // [64][256]           (64 KB)
    // post-barrier reuse of the xs region:
    float* zZ    = xs;                      // [512]
    float* zQ    = xs + 512;                // [512]
    float* sc_sh = xs + 1024;               // [64]
    float* bi_sh = xs + 1088;               // [64]
    float* s_sh  = xs + 1152;               // [8]
    __shared__ float sred[8];

    const int t    = threadIdx.x;
    const int tile = blockIdx.x;
    const int b    = tile >> 4;
    const int nb   = tile & 15;
    const int n0   = nb * TILE_N;

    // ---- kick off x tile loads (cp.async) ----
    const float4* x4 = (const float4*)(x + ((size_t)b * CC) * NN + n0);
    #pragma unroll
    for (int i = 0; i < 16; i++) {
        int idx = i * 256 + t;
        int c = idx >> 6, j = idx & 63;
        cpa16(xs + c * TILE_N + j * 4, x4 + c * (NN / 4) + j);
    }
    asm volatile("cp.async.commit_group;" ::: "memory");

    // ---- overlap: tanh(w)² partial for this 256-wide n-slice ----
    {
        float vv = tanhf(wvec[b * NN + n0 + t]);
        vv = fmaxf(vv, 0.f);
        float sp = vv * vv;
        #pragma unroll
        for (int off = 16; off > 0; off >>= 1)
            sp += __shfl_xor_sync(0xFFFFFFFFu, sp, off);
        if ((t & 31) == 0) sred[t >> 5] = sp;
    }

    // ---- overlap: W dup-packed (transposed): wt2[c][o] = {W[o,c], W[o,c]} --
    #pragma unroll
    for (int i = 0; i < 16; i++) {
        int idx = i * 256 + t;
        wt2[(idx & 63) * 64 + (idx >> 6)] = packdup(W[idx]);
    }

    asm volatile("cp.async.wait_group 0;" ::: "memory");
    __syncthreads();
    if (t == 0) {
        float s = 0.f;
        #pragma unroll
        for (int i = 0; i < 8; i++) s += sred[i];
        g_spart[tile] = s;
    }

    const int wid = t >> 5, lane = t & 31;
    const int o0 = wid * 8;
    const float* xA = xs + lane * 4;        // conflict-free (banks 4l..4l+3)
    const float* xB = xs + 128 + lane * 4;

    u64 acc[8][4];
    #pragma unroll
    for (int i = 0; i < 8; i++)
        #pragma unroll
        for (int j = 0; j < 4; j++) acc[i][j] = 0ull;

    #pragma unroll 4
    for (int c = 0; c < 64; c++) {
        const u64* wrow = wt2 + c * 64 + o0;
        ulonglong2 w01 = *(const ulonglong2*)(wrow);      // broadcast
        ulonglong2 w23 = *(const ulonglong2*)(wrow + 2);
        ulonglong2 w45 = *(const ulonglong2*)(wrow + 4);
        ulonglong2 w67 = *(const ulonglong2*)(wrow + 6);
        ulonglong2 xa = *(const ulonglong2*)(xA + c * TILE_N);
        ulonglong2 xb = *(const ulonglong2*)(xB + c * TILE_N);
        u64 wv[8] = {w01.x, w01.y, w23.x, w23.y, w45.x, w45.y, w67.x, w67.y};
        #pragma unroll
        for (int i = 0; i < 8; i++) {
            acc[i][0] = ffma2(wv[i], xa.x, acc[i][0]);
            acc[i][1] = ffma2(wv[i], xa.y, acc[i][1]);
            acc[i][2] = ffma2(wv[i], xb.x, acc[i][2]);
            acc[i][3] = ffma2(wv[i], xb.y, acc[i][3]);
        }
    }

    // ---- per-o stats partials (no z write!) ----
    #pragma unroll
    for (int i = 0; i < 8; i++) {
        float v0, v1, v2, v3, v4, v5, v6, v7;
        unpack2(acc[i][0], v0, v1);
        unpack2(acc[i][1], v2, v3);
        unpack2(acc[i][2], v4, v5);
        unpack2(acc[i][3], v6, v7);
        float s = ((v0 + v1) + (v2 + v3)) + ((v4 + v5) + (v6 + v7));
        float q = fmaf(v0, v0, fmaf(v1, v1, fmaf(v2, v2, fmaf(v3, v3,
                  fmaf(v4, v4, fmaf(v5, v5, fmaf(v6, v6, v7 * v7)))))));
        #pragma unroll
        for (int off = 16; off > 0; off >>= 1) {
            s += __shfl_xor_sync(0xFFFFFFFFu, s, off);
            q += __shfl_xor_sync(0xFFFFFFFFu, q, off);
        }
        if (lane == 0) {
            g_psum[(b * CC + (o0 + i)) * NTB + nb] = s;
            g_psq [(b * CC + (o0 + i)) * NTB + nb] = q;
        }
    }

    // ---- publish + grid barrier ----
    __threadfence();
    grid_barrier();

    // ---- redundant finalize (every block; partials are L2-resident) ----
    // s_b: warp w reduces batch w's 16 tile partials
    if (wid < 8) {
        float sp = (lane < NTB) ? g_spart[wid * NTB + lane] : 0.f;
        #pragma unroll
        for (int off = 8; off > 0; off >>= 1)
            sp += __shfl_xor_sync(0xFFFFFFFFu, sp, off);
        if (lane == 0) s_sh[wid] = sp;
    }
    // Z,Q: thread t reduces rows t and t+256 (16 contiguous floats each)
    #pragma unroll
    for (int k = 0; k < 2; k++) {
        int bo = t + k * 256;
        const float4* p4 = (const float4*)(g_psum + bo * NTB);
        const float4* q4 = (const float4*)(g_psq  + bo * NTB);
        float Z = 0.f, Q = 0.f;
        #pragma unroll
        for (int i = 0; i < NTB / 4; i++) {
            float4 a = p4[i], c = q4[i];
            Z += (a.x + a.y) + (a.z + a.w);
            Q += (c.x + c.y) + (c.z + c.w);
        }
        zZ[bo] = Z; zQ[bo] = Q;
    }
    __syncthreads();

    // per-o closed-form BN -> scale/bias for THIS block's batch b
    if (t < CC) {
        const int o = t;
        float cb = conv_b[o];
        float alpha_b = 0.f, off_b = 0.f;
        float mean_acc = 0.f, sq_acc = 0.f;
        #pragma unroll
        for (int bb = 0; bb < BB; bb++) {
            float s = s_sh[bb];
            float a = 1.f / (1.f + (float)NN * s);
            float Z = zZ[bb * CC + o];
            float Q = zQ[bb * CC + o];
            float off = a * s * Z + cb;
            if (bb == b) { alpha_b = a; off_b = off; }
            mean_acc += a * Z + (float)NN * off;
            sq_acc   += a * a * Q + 2.f * a * off * Z + (float)NN * off * off;
        }
        const float inv_cnt = 1.f / (float)(BB * NN);
        float mean = mean_acc * inv_cnt;
        float var  = sq_acc * inv_cnt - mean * mean;
        float invstd = rsqrtf(var + 1e-5f);
        float g = gamma[o] * invstd;
        sc_sh[o] = alpha_b * g;
        bi_sh[o] = (off_b - mean) * g + beta[o];
    }
    __syncthreads();

    // ---- epilogue straight from registers ----
    #pragma unroll
    for (int i = 0; i < 8; i++) {
        const int o = o0 + i;
        const float sc = sc_sh[o];
        const float bi = bi_sh[o];
        float v0, v1, v2, v3, v4, v5, v6, v7;
        unpack2(acc[i][0], v0, v1);
        unpack2(acc[i][1], v2, v3);
        unpack2(acc[i][2], v4, v5);
        unpack2(acc[i][3], v6, v7);
        float4 ra, rb;
        ra.x = fmaxf(fmaf(sc, v0, bi), 0.f);
        ra.y = fmaxf(fmaf(sc, v1, bi), 0.f);
        ra.z = fmaxf(fmaf(sc, v2, bi), 0.f);
        ra.w = fmaxf(fmaf(sc, v3, bi), 0.f);
        rb.x = fmaxf(fmaf(sc, v4, bi), 0.f);
        rb.y = fmaxf(fmaf(sc, v5, bi), 0.f);
        rb.z = fmaxf(fmaf(sc, v6, bi), 0.f);
        rb.w = fmaxf(fmaf(sc, v7, bi), 0.f);
        float* oo = out + ((size_t)(b * CC + o)) * NN + n0;
        *(float4*)(oo + lane * 4)       = ra;
        *(float4*)(oo + 128 + lane * 4) = rb;
    }
}

extern "C" void kernel_launch(void* const* d_in, const int* in_sizes, int n_in,
                              void* d_out, int out_size) {
    const float* x      = (const float*)d_in[0];  // [8,64,4096,1]
    const float* w      = (const float*)d_in[1];  // [8,4096]
    const float* conv_w = (const float*)d_in[2];  // [64,64,1,1]
    const float* conv_b = (const float*)d_in[3];  // [64]
    const float* gamma  = (const float*)d_in[4];  // [64]
    const float* beta   = (const float*)d_in[5];  // [64]
    float* out = (float*)d_out;

    cudaFuncSetAttribute(fused,
                         cudaFuncAttributeMaxDynamicSharedMemorySize, 98304);
    fused<<<TILES, 256, 98304>>>(x, w, conv_w, conv_b, gamma, beta, out);
}

// round 13
// speedup vs baseline: 1.3966x; 1.0498x over previous
#include <cuda_runtime.h>
#include <math.h>

#define BB 8
#define CC 64
#define NN 4096
#define TILE_N 256
#define NTB (NN/TILE_N)      // 16 n-tiles per batch
#define TILES (BB*NTB)       // 128 blocks (=grid, 1 CTA/SM, co-resident)
#define NTHR 512

typedef unsigned long long u64;

// Scratch (allocation-free: __device__ globals)
__device__ float g_psum[BB*CC*NTB];        // partial Σz   [b][o][nb]
__device__ float g_psq [BB*CC*NTB];        // partial Σz²  [b][o][nb]
__device__ float g_spart[TILES];           // partial s_b  [b][nb]
__device__ unsigned int g_bar = 0;         // monotonic grid barrier

// ---- f32x2 packed helpers (sm_103a) ----
__device__ __forceinline__ u64 ffma2(u64 a, u64 b, u64 c) {
    u64 d;
    asm("fma.rn.f32x2 %0, %1, %2, %3;" : "=l"(d) : "l"(a), "l"(b), "l"(c));
    return d;
}
__device__ __forceinline__ u64 packdup(float v) {
    u64 r;
    asm("mov.b64 %0, {%1, %2};" : "=l"(r) : "f"(v), "f"(v));
    return r;
}
__device__ __forceinline__ void unpack2(u64 v, float& lo, float& hi) {
    asm("mov.b64 {%0, %1}, %2;" : "=f"(lo), "=f"(hi) : "l"(v));
}
__device__ __forceinline__ void cpa16(void* smem, const void* g) {
    unsigned int a = (unsigned int)__cvta_generic_to_shared(smem);
    asm volatile("cp.async.cg.shared.global [%0], [%1], 16;" :: "r"(a), "l"(g));
}

// Replay-safe grid barrier (single round per launch).
__device__ __forceinline__ void grid_barrier() {
    __syncthreads();
    if (threadIdx.x == 0) {
        unsigned int old;
        asm volatile("atom.release.gpu.global.add.u32 %0, [%1], 1;"
                     : "=r"(old) : "l"(&g_bar) : "memory");
        unsigned int target = (old / TILES + 1u) * TILES;
        unsigned int v;
        do {
            asm volatile("ld.acquire.gpu.u32 %0, [%1];" : "=r"(v) : "l"(&g_bar));
        } while ((int)(v - target) < 0);
    }
    __syncthreads();
}

// ============================================================================
// Fused: GEMM (64o × 256n tile, 512 threads / 16 warps, warp-per-4o) ->
// stats partials -> grid barrier -> redundant finalize -> epilogue from regs.
// Per c-iter per warp: 2 broadcast LDS.128 (w) + 2 conflict-free LDS.128 (x)
// + 16 FFMA2  =>  LDS:FMA2 = 1:4, 4 warps/SMSP to hide latency.
// ============================================================================
__global__ __launch_bounds__(NTHR, 1)
void fused(const float* __restrict__ x,
           const float* __restrict__ wvec,
           const float* __restrict__ W,
           const float* __restrict__ conv_b,
           const float* __restrict__ gamma,
           const float* __restrict__ beta,
           float* __restrict__ out)
{
    extern __shared__ char sm[];
    u64*   wt2 = (u64*)sm;                  // [64][64] dup pairs (32 KB)
    float* xs  = (float*)(sm + 32768);      // [64][256]           (64 KB)
    // post-barrier reuse of the xs region:
    float* zZ    = xs;                      // [512]
    float* zQ    = xs + 512;                // [512]
    float* sc_sh = xs + 1024;               // [64]
    float* bi_sh = xs + 1088;               // [64]
    float* s_sh  = xs + 1152;               // [8]
    __shared__ float sred[8];

    const int t    = threadIdx.x;
    const int tile = blockIdx.x;
    const int b    = tile >> 4;
    const int nb   = tile & 15;
    const int n0   = nb * TILE_N;

    // ---- kick off x tile loads (cp.async): 4096 float4, 8 per thread ----
    const float4* x4 = (const float4*)(x + ((size_t)b * CC) * NN + n0);
    #pragma unroll
    for (int i = 0; i < 8; i++) {
        int idx = i * NTHR + t;
        int c = idx >> 6, j = idx & 63;
        cpa16(xs + c * TILE_N + j * 4, x4 + c * (NN / 4) + j);
    }
    asm volatile("cp.async.commit_group;" ::: "memory");

    // ---- overlap: tanh(w)² partial for this 256-wide n-slice ----
    if (t < 256) {
        float vv = tanhf(wvec[b * NN + n0 + t]);
        vv = fmaxf(vv, 0.f);
        float sp = vv * vv;
        #pragma unroll
        for (int off = 16; off > 0; off >>= 1)
            sp += __shfl_xor_sync(0xFFFFFFFFu, sp, off);
        if ((t & 31) == 0) sred[t >> 5] = sp;
    }

    // ---- overlap: W dup-packed (transposed): wt2[c][o] = {W[o,c], W[o,c]} --
    #pragma unroll
    for (int i = 0; i < 8; i++) {
        int idx = i * NTHR + t;
        wt2[(idx & 63) * 64 + (idx >> 6)] = packdup(W[idx]);
    }

    asm volatile("cp.async.wait_group 0;" ::: "memory");
    __syncthreads();
    if (t == 0) {
        float s = 0.f;
        #pragma unroll
        for (int i = 0; i < 8; i++) s += sred[i];
        g_spart[tile] = s;
    }

    const int wid = t >> 5, lane = t & 31;   // wid 0..15
    const int o0 = wid * 4;                  // 4 o's per warp
    const float* xA = xs + lane * 4;         // conflict-free (banks 4l..4l+3)
    const float* xB = xs + 128 + lane * 4;

    u64 acc[4][4];
    #pragma unroll
    for (int i = 0; i < 4; i++)
        #pragma unroll
        for (int j = 0; j < 4; j++) acc[i][j] = 0ull;

    #pragma unroll 8
    for (int c = 0; c < 64; c++) {
        const u64* wrow = wt2 + c * 64 + o0;
        ulonglong2 w01 = *(const ulonglong2*)(wrow);      // broadcast
        ulonglong2 w23 = *(const ulonglong2*)(wrow + 2);  // broadcast
        ulonglong2 xa = *(const ulonglong2*)(xA + c * TILE_N);
        ulonglong2 xb = *(const ulonglong2*)(xB + c * TILE_N);
        u64 wv[4] = {w01.x, w01.y, w23.x, w23.y};
        #pragma unroll
        for (int i = 0; i < 4; i++) {
            acc[i][0] = ffma2(wv[i], xa.x, acc[i][0]);
            acc[i][1] = ffma2(wv[i], xa.y, acc[i][1]);
            acc[i][2] = ffma2(wv[i], xb.x, acc[i][2]);
            acc[i][3] = ffma2(wv[i], xb.y, acc[i][3]);
        }
    }

    // ---- per-o stats partials (no z write) ----
    #pragma unroll
    for (int i = 0; i < 4; i++) {
        float v0, v1, v2, v3, v4, v5, v6, v7;
        unpack2(acc[i][0], v0, v1);
        unpack2(acc[i][1], v2, v3);
        unpack2(acc[i][2], v4, v5);
        unpack2(acc[i][3], v6, v7);
        float s = ((v0 + v1) + (v2 + v3)) + ((v4 + v5) + (v6 + v7));
        float q = fmaf(v0, v0, fmaf(v1, v1, fmaf(v2, v2, fmaf(v3, v3,
                  fmaf(v4, v4, fmaf(v5, v5, fmaf(v6, v6, v7 * v7)))))));
        #pragma unroll
        for (int off = 16; off > 0; off >>= 1) {
            s += __shfl_xor_sync(0xFFFFFFFFu, s, off);
            q += __shfl_xor_sync(0xFFFFFFFFu, q, off);
        }
        if (lane == 0) {
            g_psum[(b * CC + (o0 + i)) * NTB + nb] = s;
            g_psq [(b * CC + (o0 + i)) * NTB + nb] = q;
        }
    }

    // ---- publish + grid barrier ----
    __threadfence();
    grid_barrier();

    // ---- redundant finalize (every block; partials are L2-resident) ----
    if (wid < 8) {       // s_b: warp wid reduces batch wid's 16 tile partials
        float sp = (lane < NTB) ? g_spart[wid * NTB + lane] : 0.f;
        #pragma unroll
        for (int off = 8; off > 0; off >>= 1)
            sp += __shfl_xor_sync(0xFFFFFFFFu, sp, off);
        if (lane == 0) s_sh[wid] = sp;
    }
    {   // Z,Q: thread t reduces row t (16 contiguous floats each array)
        const float4* p4 = (const float4*)(g_psum + t * NTB);
        const float4* q4 = (const float4*)(g_psq  + t * NTB);
        float Z = 0.f, Q = 0.f;
        #pragma unroll
        for (int i = 0; i < NTB / 4; i++) {
            float4 a = p4[i], c = q4[i];
            Z += (a.x + a.y) + (a.z + a.w);
            Q += (c.x + c.y) + (c.z + c.w);
        }
        zZ[t] = Z; zQ[t] = Q;
    }
    __syncthreads();

    if (t < CC) {        // per-o closed-form BN -> scale/bias for batch b
        const int o = t;
        float cb = conv_b[o];
        float alpha_b = 0.f, off_b = 0.f;
        float mean_acc = 0.f, sq_acc = 0.f;
        #pragma unroll
        for (int bb = 0; bb < BB; bb++) {
            float s = s_sh[bb];
            float a = 1.f / (1.f + (float)NN * s);
            float Z = zZ[bb * CC + o];
            float Q = zQ[bb * CC + o];
            float off = a * s * Z + cb;
            if (bb == b) { alpha_b = a; off_b = off; }
            mean_acc += a * Z + (float)NN * off;
            sq_acc   += a * a * Q + 2.f * a * off * Z + (float)NN * off * off;
        }
        const float inv_cnt = 1.f / (float)(BB * NN);
        float mean = mean_acc * inv_cnt;
        float var  = sq_acc * inv_cnt - mean * mean;
        float invstd = rsqrtf(var + 1e-5f);
        float g = gamma[o] * invstd;
        sc_sh[o] = alpha_b * g;
        bi_sh[o] = (off_b - mean) * g + beta[o];
    }
    __syncthreads();

    // ---- epilogue straight from registers ----
    #pragma unroll
    for (int i = 0; i < 4; i++) {
        const int o = o0 + i;
        const float sc = sc_sh[o];
        const float bi = bi_sh[o];
        float v0, v1, v2, v3, v4, v5, v6, v7;
        unpack2(acc[i][0], v0, v1);
        unpack2(acc[i][1], v2, v3);
        unpack2(acc[i][2], v4, v5);
        unpack2(acc[i][3], v6, v7);
        float4 ra, rb;
        ra.x = fmaxf(fmaf(sc, v0, bi), 0.f);
        ra.y = fmaxf(fmaf(sc, v1, bi), 0.f);
        ra.z = fmaxf(fmaf(sc, v2, bi), 0.f);
        ra.w = fmaxf(fmaf(sc, v3, bi), 0.f);
        rb.x = fmaxf(fmaf(sc, v4, bi), 0.f);
        rb.y = fmaxf(fmaf(sc, v5, bi), 0.f);
        rb.z = fmaxf(fmaf(sc, v6, bi), 0.f);
        rb.w = fmaxf(fmaf(sc, v7, bi), 0.f);
        float* oo = out + ((size_t)(b * CC + o)) * NN + n0;
        *(float4*)(oo + lane * 4)       = ra;
        *(float4*)(oo + 128 + lane * 4) = rb;
    }
}

extern "C" void kernel_launch(void* const* d_in, const int* in_sizes, int n_in,
                              void* d_out, int out_size) {
    const float* x      = (const float*)d_in[0];  // [8,64,4096,1]
    const float* w      = (const float*)d_in[1];  // [8,4096]
    const float* conv_w = (const float*)d_in[2];  // [64,64,1,1]
    const float* conv_b = (const float*)d_in[3];  // [64]
    const float* gamma  = (const float*)d_in[4];  // [64]
    const float* beta   = (const float*)d_in[5];  // [64]
    float* out = (float*)d_out;

    cudaFuncSetAttribute(fused,
                         cudaFuncAttributeMaxDynamicSharedMemorySize, 98304);
    fused<<<TILES, NTHR, 98304>>>(x, w, conv_w, conv_b, gamma, beta, out);
}

// round 14
// speedup vs baseline: 1.5195x; 1.0880x over previous
#include <cuda_runtime.h>
#include <math.h>

#define BB 8
#define CC 64
#define NN 4096
#define TILE_N 256
#define NTB (NN/TILE_N)      // 16 n-tiles per batch
#define TILES (BB*NTB)       // 128 blocks (=grid, 1 CTA/SM, co-resident)
#define NTHR 512

typedef unsigned long long u64;

// Scratch (allocation-free: __device__ globals)
__device__ float g_psum[BB*CC*NTB];        // partial Σz   [b][o][nb]
__device__ float g_psq [BB*CC*NTB];        // partial Σz²  [b][o][nb]
__device__ float g_spart[TILES];           // partial s_b  [b][nb]
__device__ unsigned int g_bar = 0;         // monotonic grid barrier

// ---- f32x2 packed helpers (sm_103a) ----
__device__ __forceinline__ u64 ffma2(u64 a, u64 b, u64 c) {
    u64 d;
    asm("fma.rn.f32x2 %0, %1, %2, %3;" : "=l"(d) : "l"(a), "l"(b), "l"(c));
    return d;
}
__device__ __forceinline__ u64 packdup(float v) {
    u64 r;
    asm("mov.b64 %0, {%1, %2};" : "=l"(r) : "f"(v), "f"(v));
    return r;
}
__device__ __forceinline__ void unpack2(u64 v, float& lo, float& hi) {
    asm("mov.b64 {%0, %1}, %2;" : "=f"(lo), "=f"(hi) : "l"(v));
}

// Replay-safe grid barrier (single round per launch).
__device__ __forceinline__ void grid_barrier() {
    __syncthreads();
    if (threadIdx.x == 0) {
        unsigned int old;
        asm volatile("atom.release.gpu.global.add.u32 %0, [%1], 1;"
                     : "=r"(old) : "l"(&g_bar) : "memory");
        unsigned int target = (old / TILES + 1u) * TILES;
        unsigned int v;
        do {
            asm volatile("ld.acquire.gpu.u32 %0, [%1];" : "=r"(v) : "l"(&g_bar));
        } while ((int)(v - target) < 0);
    }
    __syncthreads();
}

// ============================================================================
// Fused: GEMM (64o × 256n tile, 512 threads / 16 warps, warp-per-4o,
// SOFTWARE-PIPELINED inner loop) -> stats partials -> grid barrier ->
// redundant finalize -> epilogue from registers.
// ============================================================================
__global__ __launch_bounds__(NTHR, 1)
void fused(const float* __restrict__ x,
           const float* __restrict__ wvec,
           const float* __restrict__ W,
           const float* __restrict__ conv_b,
           const float* __restrict__ gamma,
           const float* __restrict__ beta,
           float* __restrict__ out)
{
    extern __shared__ char sm[];
    u64*   wt2 = (u64*)sm;                  // [64][64] dup pairs (32 KB)
    float* xs  = (float*)(sm + 32768);      // [64][256]           (64 KB)
    // post-barrier reuse of the xs region:
    float* zZ    = xs;                      // [512]
    float* zQ    = xs + 512;                // [512]
    float* sc_sh = xs + 1024;               // [64]
    float* bi_sh = xs + 1088;               // [64]
    float* s_sh  = xs + 1152;               // [8]
    __shared__ float sred[8];

    const int t    = threadIdx.x;
    const int tile = blockIdx.x;
    const int b    = tile >> 4;
    const int nb   = tile & 15;
    const int n0   = nb * TILE_N;

    // ---- x tile: direct LDG -> STS (measured faster than cp.async here) ----
    const float4* x4 = (const float4*)(x + ((size_t)b * CC) * NN + n0);
    #pragma unroll
    for (int i = 0; i < 8; i++) {
        int idx = i * NTHR + t;
        int c = idx >> 6, j = idx & 63;
        ((float4*)(xs + c * TILE_N))[j] = x4[c * (NN / 4) + j];
    }

    // ---- tanh(w)² partial for this 256-wide n-slice ----
    if (t < 256) {
        float vv = tanhf(wvec[b * NN + n0 + t]);
        vv = fmaxf(vv, 0.f);
        float sp = vv * vv;
        #pragma unroll
        for (int off = 16; off > 0; off >>= 1)
            sp += __shfl_xor_sync(0xFFFFFFFFu, sp, off);
        if ((t & 31) == 0) sred[t >> 5] = sp;
    }

    // ---- W dup-packed (transposed): wt2[c][o] = {W[o,c], W[o,c]} ----
    #pragma unroll
    for (int i = 0; i < 8; i++) {
        int idx = i * NTHR + t;
        wt2[(idx & 63) * 64 + (idx >> 6)] = packdup(W[idx]);
    }
    __syncthreads();
    if (t == 0) {
        float s = 0.f;
        #pragma unroll
        for (int i = 0; i < 8; i++) s += sred[i];
        g_spart[tile] = s;
    }

    const int wid = t >> 5, lane = t & 31;   // wid 0..15
    const int o0 = wid * 4;                  // 4 o's per warp
    const float* xA = xs + lane * 4;         // conflict-free (banks 4l..4l+3)
    const float* xB = xs + 128 + lane * 4;
    const u64*   wp = wt2 + o0;

    u64 acc[4][4];
    #pragma unroll
    for (int i = 0; i < 4; i++)
        #pragma unroll
        for (int j = 0; j < 4; j++) acc[i][j] = 0ull;

    // ---- software-pipelined c-loop: prefetch c+1 before FMAs of c ----
    ulonglong2 cw01 = *(const ulonglong2*)(wp);
    ulonglong2 cw23 = *(const ulonglong2*)(wp + 2);
    ulonglong2 cxa  = *(const ulonglong2*)(xA);
    ulonglong2 cxb  = *(const ulonglong2*)(xB);

    #pragma unroll 7
    for (int c = 0; c < 63; c++) {
        ulonglong2 nw01 = *(const ulonglong2*)(wp + (c + 1) * 64);
        ulonglong2 nw23 = *(const ulonglong2*)(wp + (c + 1) * 64 + 2);
        ulonglong2 nxa  = *(const ulonglong2*)(xA + (c + 1) * TILE_N);
        ulonglong2 nxb  = *(const ulonglong2*)(xB + (c + 1) * TILE_N);

        acc[0][0] = ffma2(cw01.x, cxa.x, acc[0][0]);
        acc[0][1] = ffma2(cw01.x, cxa.y, acc[0][1]);
        acc[0][2] = ffma2(cw01.x, cxb.x, acc[0][2]);
        acc[0][3] = ffma2(cw01.x, cxb.y, acc[0][3]);
        acc[1][0] = ffma2(cw01.y, cxa.x, acc[1][0]);
        acc[1][1] = ffma2(cw01.y, cxa.y, acc[1][1]);
        acc[1][2] = ffma2(cw01.y, cxb.x, acc[1][2]);
        acc[1][3] = ffma2(cw01.y, cxb.y, acc[1][3]);
        acc[2][0] = ffma2(cw23.x, cxa.x, acc[2][0]);
        acc[2][1] = ffma2(cw23.x, cxa.y, acc[2][1]);
        acc[2][2] = ffma2(cw23.x, cxb.x, acc[2][2]);
        acc[2][3] = ffma2(cw23.x, cxb.y, acc[2][3]);
        acc[3][0] = ffma2(cw23.y, cxa.x, acc[3][0]);
        acc[3][1] = ffma2(cw23.y, cxa.y, acc[3][1]);
        acc[3][2] = ffma2(cw23.y, cxb.x, acc[3][2]);
        acc[3][3] = ffma2(cw23.y, cxb.y, acc[3][3]);

        cw01 = nw01; cw23 = nw23; cxa = nxa; cxb = nxb;
    }
    // final iteration (c = 63)
    acc[0][0] = ffma2(cw01.x, cxa.x, acc[0][0]);
    acc[0][1] = ffma2(cw01.x, cxa.y, acc[0][1]);
    acc[0][2] = ffma2(cw01.x, cxb.x, acc[0][2]);
    acc[0][3] = ffma2(cw01.x, cxb.y, acc[0][3]);
    acc[1][0] = ffma2(cw01.y, cxa.x, acc[1][0]);
    acc[1][1] = ffma2(cw01.y, cxa.y, acc[1][1]);
    acc[1][2] = ffma2(cw01.y, cxb.x, acc[1][2]);
    acc[1][3] = ffma2(cw01.y, cxb.y, acc[1][3]);
    acc[2][0] = ffma2(cw23.x, cxa.x, acc[2][0]);
    acc[2][1] = ffma2(cw23.x, cxa.y, acc[2][1]);
    acc[2][2] = ffma2(cw23.x, cxb.x, acc[2][2]);
    acc[2][3] = ffma2(cw23.x, cxb.y, acc[2][3]);
    acc[3][0] = ffma2(cw23.y, cxa.x, acc[3][0]);
    acc[3][1] = ffma2(cw23.y, cxa.y, acc[3][1]);
    acc[3][2] = ffma2(cw23.y, cxb.x, acc[3][2]);
    acc[3][3] = ffma2(cw23.y, cxb.y, acc[3][3]);

    // ---- per-o stats partials ----
    #pragma unroll
    for (int i = 0; i < 4; i++) {
        float v0, v1, v2, v3, v4, v5, v6, v7;
        unpack2(acc[i][0], v0, v1);
        unpack2(acc[i][1], v2, v3);
        unpack2(acc[i][2], v4, v5);
        unpack2(acc[i][3], v6, v7);
        float s = ((v0 + v1) + (v2 + v3)) + ((v4 + v5) + (v6 + v7));
        float q = fmaf(v0, v0, fmaf(v1, v1, fmaf(v2, v2, fmaf(v3, v3,
                  fmaf(v4, v4, fmaf(v5, v5, fmaf(v6, v6, v7 * v7)))))));
        #pragma unroll
        for (int off = 16; off > 0; off >>= 1) {
            s += __shfl_xor_sync(0xFFFFFFFFu, s, off);
            q += __shfl_xor_sync(0xFFFFFFFFu, q, off);
        }
        if (lane == 0) {
            g_psum[(b * CC + (o0 + i)) * NTB + nb] = s;
            g_psq [(b * CC + (o0 + i)) * NTB + nb] = q;
        }
    }

    // ---- publish + grid barrier ----
    __threadfence();
    grid_barrier();

    // ---- redundant finalize (every block; partials are L2-resident) ----
    if (wid < 8) {       // s_b: warp wid reduces batch wid's 16 tile partials
        float sp = (lane < NTB) ? g_spart[wid * NTB + lane] : 0.f;
        #pragma unroll
        for (int off = 8; off > 0; off >>= 1)
            sp += __shfl_xor_sync(0xFFFFFFFFu, sp, off);
        if (lane == 0) s_sh[wid] = sp;
    }
    {   // Z,Q: thread t reduces row t (16 contiguous floats each array)
        const float4* p4 = (const float4*)(g_psum + t * NTB);
        const float4* q4 = (const float4*)(g_psq  + t * NTB);
        float Z = 0.f, Q = 0.f;
        #pragma unroll
        for (int i = 0; i < NTB / 4; i++) {
            float4 a = p4[i], c = q4[i];
            Z += (a.x + a.y) + (a.z + a.w);
            Q += (c.x + c.y) + (c.z + c.w);
        }
        zZ[t] = Z; zQ[t] = Q;
    }
    __syncthreads();

    if (t < CC) {        // per-o closed-form BN -> scale/bias for batch b
        const int o = t;
        float cb = conv_b[o];
        float alpha_b = 0.f, off_b = 0.f;
        float mean_acc = 0.f, sq_acc = 0.f;
        #pragma unroll
        for (int bb = 0; bb < BB; bb++) {
            float s = s_sh[bb];
            float a = 1.f / (1.f + (float)NN * s);
            float Z = zZ[bb * CC + o];
            float Q = zQ[bb * CC + o];
            float off = a * s * Z + cb;
            if (bb == b) { alpha_b = a; off_b = off; }
            mean_acc += a * Z + (float)NN * off;
            sq_acc   += a * a * Q + 2.f * a * off * Z + (float)NN * off * off;
        }
        const float inv_cnt = 1.f / (float)(BB * NN);
        float mean = mean_acc * inv_cnt;
        float var  = sq_acc * inv_cnt - mean * mean;
        float invstd = rsqrtf(var + 1e-5f);
        float g = gamma[o] * invstd;
        sc_sh[o] = alpha_b * g;
        bi_sh[o] = (off_b - mean) * g + beta[o];
    }
    __syncthreads();

    // ---- epilogue straight from registers ----
    #pragma unroll
    for (int i = 0; i < 4; i++) {
        const int o = o0 + i;
        const float sc = sc_sh[o];
        const float bi = bi_sh[o];
        float v0, v1, v2, v3, v4, v5, v6, v7;
        unpack2(acc[i][0], v0, v1);
        unpack2(acc[i][1], v2, v3);
        unpack2(acc[i][2], v4, v5);
        unpack2(acc[i][3], v6, v7);
        float4 ra, rb;
        ra.x = fmaxf(fmaf(sc, v0, bi), 0.f);
        ra.y = fmaxf(fmaf(sc, v1, bi), 0.f);
        ra.z = fmaxf(fmaf(sc, v2, bi), 0.f);
        ra.w = fmaxf(fmaf(sc, v3, bi), 0.f);
        rb.x = fmaxf(fmaf(sc, v4, bi), 0.f);
        rb.y = fmaxf(fmaf(sc, v5, bi), 0.f);
        rb.z = fmaxf(fmaf(sc, v6, bi), 0.f);
        rb.w = fmaxf(fmaf(sc, v7, bi), 0.f);
        float* oo = out + ((size_t)(b * CC + o)) * NN + n0;
        *(float4*)(oo + lane * 4)       = ra;
        *(float4*)(oo + 128 + lane * 4) = rb;
    }
}

extern "C" void kernel_launch(void* const* d_in, const int* in_sizes, int n_in,
                              void* d_out, int out_size) {
    const float* x      = (const float*)d_in[0];  // [8,64,4096,1]
    const float* w      = (const float*)d_in[1];  // [8,4096]
    const float* conv_w = (const float*)d_in[2];  // [64,64,1,1]
    const float* conv_b = (const float*)d_in[3];  // [64]
    const float* gamma  = (const float*)d_in[4];  // [64]
    const float* beta   = (const float*)d_in[5];  // [64]
    float* out = (float*)d_out;

    cudaFuncSetAttribute(fused,
                         cudaFuncAttributeMaxDynamicSharedMemorySize, 98304);
    fused<<<TILES, NTHR, 98304>>>(x, w, conv_w, conv_b, gamma, beta, out);
}